// round 1
// baseline (speedup 1.0000x reference)
#include <cuda_runtime.h>

// Problem constants
#define Bsz  128
#define Tlen 1024
#define H1   128
#define H2   64
#define NB1  64           // layer-1 blocks, 2 h-dims each
#define NB2  64           // layer-2 blocks, 1 h-dim each
#define NBLK 128
#define NTHR 256

// Persistent state (no allocations allowed): double-buffered hidden states,
// stored transposed [dim][batch] so owner writes and reader loads are coalesced.
__device__ float    g_h1[2][H1][Bsz];
__device__ float    g_h2[2][H2][Bsz];
__device__ unsigned g_cnt;            // monotonic global-barrier counter

__device__ __forceinline__ float sigm(float v) { return 1.0f / (1.0f + __expf(-v)); }

__device__ __forceinline__ unsigned ld_acq(const unsigned* p) {
    unsigned v;
    asm volatile("ld.global.acquire.gpu.u32 %0, [%1];" : "=r"(v) : "l"(p) : "memory");
    return v;
}

// Grid-wide barrier: monotonic counter, no reset needed within a launch.
// All writers fence, funnel through block barrier, one thread arrives+spins.
__device__ __forceinline__ void gsync(unsigned target) {
    __threadfence();
    __syncthreads();
    if (threadIdx.x == 0) {
        atomicAdd(&g_cnt, 1u);
        while (ld_acq(&g_cnt) < target) { }
    }
    __syncthreads();
}

__global__ void init_kernel() {
    int i = blockIdx.x * blockDim.x + threadIdx.x;
    float* p1 = &g_h1[0][0][0];
    if (i < 2 * H1 * Bsz) p1[i] = 0.0f;
    float* p2 = &g_h2[0][0][0];
    if (i < 2 * H2 * Bsz) p2[i] = 0.0f;
    if (i == 0) g_cnt = 0u;
}

__global__ void __launch_bounds__(NTHR, 1) lstm_kernel(
    const float* __restrict__ x,      // [B][T]
    const float* __restrict__ w_ih1,  // [512][1]
    const float* __restrict__ w_hh1,  // [512][128]
    const float* __restrict__ b_ih1,
    const float* __restrict__ b_hh1,
    const float* __restrict__ w_ih2,  // [256][128]
    const float* __restrict__ w_hh2,  // [256][64]
    const float* __restrict__ b_ih2,
    const float* __restrict__ b_hh2,
    float* __restrict__ out)          // [B][64]
{
    __shared__ __align__(16) float ws1[H1][8];   // L1: ws1[k][t*4+j]
    __shared__ __align__(16) float ws2[192][4];  // L2: ws2[k][j], k<128 -> w_ih2, else w_hh2
    __shared__ float red[4][Bsz];                // L2 K-split reduction buffer

    const int blk = blockIdx.x;
    const int tid = threadIdx.x;

    if (blk < NB1) {
        // ---------------- Layer 1 block: owns h-dims d0, d0+1 ----------------
        const int d0 = blk * 2;
        for (int idx = tid; idx < H1 * 8; idx += NTHR) {
            int k = idx >> 3, g8 = idx & 7;
            int t = g8 >> 2, j = g8 & 3;   // j: 0=i,1=f,2=g,3=o
            ws1[k][g8] = w_hh1[(j * H1 + d0 + t) * H1 + k];
        }
        const int b = tid & (Bsz - 1);
        const int t = tid >> 7;
        const int d = d0 + t;
        float wih[4], bias[4];
#pragma unroll
        for (int j = 0; j < 4; j++) {
            int row = j * H1 + d;
            wih[j]  = w_ih1[row];
            bias[j] = b_ih1[row] + b_hh1[row];
        }
        __syncthreads();

        float c = 0.0f;
        const float* xr = x + b * Tlen;
        for (int r = 0; r < Tlen; r++) {
            const int pp = (r + 1) & 1;   // read parity (previous step)
            const int pc = r & 1;         // write parity (this step)
            float xv = __ldg(xr + r);
            float a0 = fmaf(xv, wih[0], bias[0]);
            float a1 = fmaf(xv, wih[1], bias[1]);
            float a2 = fmaf(xv, wih[2], bias[2]);
            float a3 = fmaf(xv, wih[3], bias[3]);
            const float* hb = &g_h1[pp][0][b];
            const float* wr = &ws1[0][t * 4];
#pragma unroll
            for (int k = 0; k < H1; k++) {
                float  hv = __ldcg(hb + k * Bsz);
                float4 w  = *reinterpret_cast<const float4*>(wr + k * 8);
                a0 = fmaf(hv, w.x, a0);
                a1 = fmaf(hv, w.y, a1);
                a2 = fmaf(hv, w.z, a2);
                a3 = fmaf(hv, w.w, a3);
            }
            float ig = sigm(a0);
            float fg = sigm(a1);
            float gg = tanhf(a2);
            float og = sigm(a3);
            c = fg * c + ig * gg;
            float h = og * tanhf(c);
            g_h1[pc][d][b] = h;
            gsync((unsigned)NBLK * (unsigned)(r + 1));
        }
    } else {
        // ---------------- Layer 2 block: owns h-dim d ----------------
        const int d = blk - NB1;
        for (int idx = tid; idx < 192 * 4; idx += NTHR) {
            int k = idx >> 2, j = idx & 3;
            ws2[k][j] = (k < H1) ? w_ih2[(j * H2 + d) * H1 + k]
                                 : w_hh2[(j * H2 + d) * H2 + (k - H1)];
        }
        const int b    = tid & (Bsz - 1);
        const int half = tid >> 7;
        float bias[4];
#pragma unroll
        for (int j = 0; j < 4; j++) bias[j] = b_ih2[j * H2 + d] + b_hh2[j * H2 + d];
        __syncthreads();

        float c = 0.0f;
        // Global round r: layer-2 computes step t2 = r-1 (one step behind L1).
        // Rounds 0..Tlen-1 are synced (matching L1); final step runs after the loop.
        for (int r = 0; r <= Tlen; r++) {
            if (r >= 1) {
                const int pp = (r + 1) & 1;
                const int pc = r & 1;
                float a0 = 0.f, a1 = 0.f, a2 = 0.f, a3 = 0.f;
                if (half == 0) {
                    const float* hb = &g_h1[pp][0][b];
#pragma unroll
                    for (int k = 0; k < 96; k++) {
                        float  hv = __ldcg(hb + k * Bsz);
                        float4 w  = *reinterpret_cast<const float4*>(&ws2[k][0]);
                        a0 = fmaf(hv, w.x, a0); a1 = fmaf(hv, w.y, a1);
                        a2 = fmaf(hv, w.z, a2); a3 = fmaf(hv, w.w, a3);
                    }
                } else {
                    const float* hb = &g_h1[pp][0][b];
#pragma unroll
                    for (int k = 96; k < H1; k++) {
                        float  hv = __ldcg(hb + k * Bsz);
                        float4 w  = *reinterpret_cast<const float4*>(&ws2[k][0]);
                        a0 = fmaf(hv, w.x, a0); a1 = fmaf(hv, w.y, a1);
                        a2 = fmaf(hv, w.z, a2); a3 = fmaf(hv, w.w, a3);
                    }
                    const float* hb2 = &g_h2[pp][0][b];
#pragma unroll
                    for (int k = 0; k < H2; k++) {
                        float  hv = __ldcg(hb2 + k * Bsz);
                        float4 w  = *reinterpret_cast<const float4*>(&ws2[H1 + k][0]);
                        a0 = fmaf(hv, w.x, a0); a1 = fmaf(hv, w.y, a1);
                        a2 = fmaf(hv, w.z, a2); a3 = fmaf(hv, w.w, a3);
                    }
                    red[0][b] = a0; red[1][b] = a1; red[2][b] = a2; red[3][b] = a3;
                }
                __syncthreads();
                if (half == 0) {
                    a0 += red[0][b] + bias[0];
                    a1 += red[1][b] + bias[1];
                    a2 += red[2][b] + bias[2];
                    a3 += red[3][b] + bias[3];
                    float ig = sigm(a0);
                    float fg = sigm(a1);
                    float gg = tanhf(a2);
                    float og = sigm(a3);
                    c = fg * c + ig * gg;
                    float h = og * tanhf(c);
                    g_h2[pc][d][b] = h;
                    if (r == Tlen) out[b * H2 + d] = h;  // final hidden -> output
                }
            }
            if (r < Tlen) gsync((unsigned)NBLK * (unsigned)(r + 1));
        }
    }
}

extern "C" void kernel_launch(void* const* d_in, const int* in_sizes, int n_in,
                              void* d_out, int out_size) {
    const float* x     = (const float*)d_in[0];
    const float* w_ih1 = (const float*)d_in[1];
    const float* w_hh1 = (const float*)d_in[2];
    const float* b_ih1 = (const float*)d_in[3];
    const float* b_hh1 = (const float*)d_in[4];
    const float* w_ih2 = (const float*)d_in[5];
    const float* w_hh2 = (const float*)d_in[6];
    const float* b_ih2 = (const float*)d_in[7];
    const float* b_hh2 = (const float*)d_in[8];
    float* out = (float*)d_out;

    init_kernel<<<128, 256>>>();
    lstm_kernel<<<NBLK, NTHR>>>(x, w_ih1, w_hh1, b_ih1, b_hh1,
                                w_ih2, w_hh2, b_ih2, b_hh2, out);
    (void)in_sizes; (void)n_in; (void)out_size;
}

// round 3
// speedup vs baseline: 1.0499x; 1.0499x over previous
#include <cuda_runtime.h>
#include <cstdint>

#define Tlen 1024
#define NCTA 128
#define NTHR 512

// ---- shared memory layout (float indices) ----
// W1 : [dl 32][gate 4][k 132pad]   layer-1 w_hh slice (k<128 valid)
// W2 : [64 rows][196pad]           layer-2 [w_ih2 | w_hh2] concat (k<192 valid)
// HC : [2 buf][b 4][196pad]        h1(0..127) ++ h2(128..191), double buffered
// A1 : [512]                       layer-1 gate partials
// A2 : [512]                       layer-2 gate partials (2 k-halves)
// XS : [b 4][1024]                 x staged for this cluster's batches
constexpr int W1_OFF = 0;
constexpr int W2_OFF = W1_OFF + 32 * 4 * 132;   // 16896
constexpr int HC_OFF = W2_OFF + 64 * 196;       // 29440
constexpr int A1_OFF = HC_OFF + 2 * 4 * 196;    // 31008
constexpr int A2_OFF = A1_OFF + 512;            // 31520
constexpr int XS_OFF = A2_OFF + 512;            // 32032
constexpr int SMEM_FLOATS = XS_OFF + 4 * 1024;  // 36128
constexpr int SMEM_BYTES = SMEM_FLOATS * 4;     // 144512 B

__device__ __forceinline__ float sigm(float v) { return 1.0f / (1.0f + __expf(-v)); }

__device__ __forceinline__ uint32_t s2u(const void* p) {
    uint32_t a;
    asm("{ .reg .u64 t; cvta.to.shared.u64 t, %1; cvt.u32.u64 %0, t; }" : "=r"(a) : "l"(p));
    return a;
}

// store 4B to the same smem offset in cluster CTA `rank`
__device__ __forceinline__ void stc(uint32_t saddr, int rank, float v) {
    uint32_t r;
    asm volatile("mapa.shared::cluster.u32 %0, %1, %2;" : "=r"(r) : "r"(saddr), "r"(rank));
    asm volatile("st.shared::cluster.f32 [%0], %1;" :: "r"(r), "f"(v) : "memory");
}

__device__ __forceinline__ void csync() {
    asm volatile("barrier.cluster.arrive.aligned;" ::: "memory");
    asm volatile("barrier.cluster.wait.aligned;" ::: "memory");
}

// packed fp32x2 FMA: acc = a*b + acc  (elementwise on two f32 lanes)
__device__ __forceinline__ void ffma2(unsigned long long& acc,
                                      unsigned long long a, unsigned long long b) {
    asm("fma.rn.f32x2 %0, %1, %2, %0;" : "+l"(acc) : "l"(a), "l"(b));
}

__device__ __forceinline__ float2 u2f2(unsigned long long u) {
    float2 f;
    asm("mov.b64 {%0, %1}, %2;" : "=f"(f.x), "=f"(f.y) : "l"(u));
    return f;
}

extern __shared__ float smf[];

__global__ void __launch_bounds__(NTHR, 1) __cluster_dims__(4, 1, 1)
lstm_cluster_kernel(
    const float* __restrict__ x,      // [128][1024]
    const float* __restrict__ w_ih1,  // [512][1]
    const float* __restrict__ w_hh1,  // [512][128]
    const float* __restrict__ b_ih1,
    const float* __restrict__ b_hh1,
    const float* __restrict__ w_ih2,  // [256][128]
    const float* __restrict__ w_hh2,  // [256][64]
    const float* __restrict__ b_ih2,
    const float* __restrict__ b_hh2,
    float* __restrict__ out)          // [128][64]
{
    const int tid = threadIdx.x;
    const int q   = blockIdx.x & 3;   // cluster rank (dim slice)
    const int cid = blockIdx.x >> 2;  // cluster id (batch group: batches 4*cid..4*cid+3)

    // ---------------- init: stage weights, x, zero hc ----------------
    for (int idx = tid; idx < 32 * 4 * 128; idx += NTHR) {
        int k = idx & 127, g = (idx >> 7) & 3, dl = idx >> 9;
        smf[W1_OFF + (dl * 4 + g) * 132 + k] = w_hh1[(g * 128 + 32 * q + dl) * 128 + k];
    }
    for (int idx = tid; idx < 64 * 192; idx += NTHR) {
        int k = idx % 192, row = idx / 192;
        int dl = row >> 2, g = row & 3;
        int gr = g * 64 + 16 * q + dl;
        smf[W2_OFF + row * 196 + k] = (k < 128) ? w_ih2[gr * 128 + k]
                                                : w_hh2[gr * 64 + (k - 128)];
    }
    for (int idx = tid; idx < 4 * 1024; idx += NTHR) {
        int b = idx >> 10, t = idx & 1023;
        smf[XS_OFF + idx] = x[(4 * cid + b) * 1024 + t];
    }
    for (int idx = tid; idx < 2 * 4 * 196; idx += NTHR) smf[HC_OFF + idx] = 0.0f;

    // ---------------- per-thread role constants ----------------
    const int b   = tid & 3;          // batch within cluster
    const int g   = (tid >> 2) & 3;   // gate (i,f,g,o)
    const int dl1 = tid >> 4;         // 0..31 : L1 dim-local
    const int dl2 = (tid >> 4) & 15;  // 0..15 : L2 dim-local
    const int kh  = tid >> 8;         // 0/1   : L2 k-half

    const int   row1  = g * 128 + 32 * q + dl1;
    const float wih1  = w_ih1[row1];
    const float bias1 = b_ih1[row1] + b_hh1[row1];

    const int cb = tid & 3, cd = tid >> 2;  // combiner decode
    float b2i = 0.f, b2f = 0.f, b2g = 0.f, b2o = 0.f;
    if (tid < 64) {
        int d2 = 16 * q + cd;
        b2i = b_ih2[0 * 64 + d2] + b_hh2[0 * 64 + d2];
        b2f = b_ih2[1 * 64 + d2] + b_hh2[1 * 64 + d2];
        b2g = b_ih2[2 * 64 + d2] + b_hh2[2 * 64 + d2];
        b2o = b_ih2[3 * 64 + d2] + b_hh2[3 * 64 + d2];
    }

    csync();  // smem of every CTA in the cluster ready

    float c1 = 0.0f, c2 = 0.0f;

    for (int i = 0; i <= Tlen; i++) {
        const int pc = i & 1, pp = pc ^ 1;

        // ---- layer-1 gate partial: a = W_hh1[row] . h1(prev) + x*w_ih1 + bias ----
        if (i < Tlen) {
            const ulonglong2* hp =
                reinterpret_cast<const ulonglong2*>(&smf[HC_OFF + pp * 784 + b * 196]);
            const ulonglong2* wp =
                reinterpret_cast<const ulonglong2*>(&smf[W1_OFF + (dl1 * 4 + g) * 132]);
            unsigned long long a0 = 0ull, a1 = 0ull;
#pragma unroll
            for (int kk = 0; kk < 32; kk++) {   // 128 k = 32 iters x 4 k (2 ffma2)
                ulonglong2 h = hp[kk];
                ulonglong2 w = wp[kk];
                ffma2(a0, h.x, w.x);
                ffma2(a1, h.y, w.y);
            }
            float2 f0 = u2f2(a0), f1 = u2f2(a1);
            smf[A1_OFF + tid] = (f0.x + f0.y) + (f1.x + f1.y) +
                                fmaf(smf[XS_OFF + b * 1024 + i], wih1, bias1);
        }

        // ---- layer-2 gate partial over k-half of [h1(prev) ++ h2(prev)] ----
        if (i >= 1) {
            const ulonglong2* hp = reinterpret_cast<const ulonglong2*>(
                &smf[HC_OFF + pp * 784 + b * 196 + kh * 96]);
            const ulonglong2* wp = reinterpret_cast<const ulonglong2*>(
                &smf[W2_OFF + (dl2 * 4 + g) * 196 + kh * 96]);
            unsigned long long a0 = 0ull, a1 = 0ull;
#pragma unroll
            for (int kk = 0; kk < 24; kk++) {   // 96 k per half = 24 iters x 4 k
                ulonglong2 h = hp[kk];
                ulonglong2 w = wp[kk];
                ffma2(a0, h.x, w.x);
                ffma2(a1, h.y, w.y);
            }
            float2 f0 = u2f2(a0), f1 = u2f2(a1);
            smf[A2_OFF + tid] = (f0.x + f0.y) + (f1.x + f1.y);
        }

        __syncthreads();

        // ---- layer-1 combine + scatter h1 to all cluster CTAs ----
        if (i < Tlen && tid < 128) {
            int base = cb + 16 * cd;  // producer tid = b + 4g + 16dl
            float ai = smf[A1_OFF + base];
            float af = smf[A1_OFF + base + 4];
            float ag = smf[A1_OFF + base + 8];
            float ao = smf[A1_OFF + base + 12];
            c1 = sigm(af) * c1 + sigm(ai) * tanhf(ag);
            float h = sigm(ao) * tanhf(c1);
            uint32_t dst = s2u(&smf[HC_OFF + pc * 784 + cb * 196 + 32 * q + cd]);
            stc(dst, 0, h); stc(dst, 1, h); stc(dst, 2, h); stc(dst, 3, h);
        }

        // ---- layer-2 combine (one step behind) + scatter h2 / final output ----
        if (i >= 1 && tid < 64) {
            int base = cb + 16 * cd;
            float ai = smf[A2_OFF + base]      + smf[A2_OFF + base + 256] + b2i;
            float af = smf[A2_OFF + base + 4]  + smf[A2_OFF + base + 260] + b2f;
            float ag = smf[A2_OFF + base + 8]  + smf[A2_OFF + base + 264] + b2g;
            float ao = smf[A2_OFF + base + 12] + smf[A2_OFF + base + 268] + b2o;
            c2 = sigm(af) * c2 + sigm(ai) * tanhf(c2 * 0.0f + ag);
            float h = sigm(ao) * tanhf(c2);
            if (i == Tlen) {
                out[(4 * cid + cb) * 64 + 16 * q + cd] = h;  // final hidden state
            } else {
                uint32_t dst =
                    s2u(&smf[HC_OFF + pc * 784 + cb * 196 + 128 + 16 * q + cd]);
                stc(dst, 0, h); stc(dst, 1, h); stc(dst, 2, h); stc(dst, 3, h);
            }
        }

        if (i < Tlen) csync();  // release our h writes / acquire peers'
    }
}

extern "C" void kernel_launch(void* const* d_in, const int* in_sizes, int n_in,
                              void* d_out, int out_size) {
    const float* x     = (const float*)d_in[0];
    const float* w_ih1 = (const float*)d_in[1];
    const float* w_hh1 = (const float*)d_in[2];
    const float* b_ih1 = (const float*)d_in[3];
    const float* b_hh1 = (const float*)d_in[4];
    const float* w_ih2 = (const float*)d_in[5];
    const float* w_hh2 = (const float*)d_in[6];
    const float* b_ih2 = (const float*)d_in[7];
    const float* b_hh2 = (const float*)d_in[8];
    float* out = (float*)d_out;

    cudaFuncSetAttribute(lstm_cluster_kernel,
                         cudaFuncAttributeMaxDynamicSharedMemorySize, SMEM_BYTES);
    lstm_cluster_kernel<<<NCTA, NTHR, SMEM_BYTES>>>(
        x, w_ih1, w_hh1, b_ih1, b_hh1, w_ih2, w_hh2, b_ih2, b_hh2, out);
    (void)in_sizes; (void)n_in; (void)out_size;
}